// round 7
// baseline (speedup 1.0000x reference)
#include <cuda_runtime.h>
#include <cstdint>
#include <cstddef>

// Problem constants
#define BB   64
#define SS   1024
#define II   256
#define HH   512
#define G4   2048              // 4*HH
#define SH   (SS*HH)
#define BSH  ((size_t)BB*SH)

// Recurrent kernel config
#define GRID_B 128             // CTAs; each owns 4 h-columns
#define TPB    256

// SMEM layout (float indices)
#define OFF_H    0                  // h_sh [512][64] floats (128 KB)
#define OFF_WD   (512*64)           // wds: 8192 ull (64 KB) = 16384 floats
#define OFF_PB   (OFF_WD + 16384)   // pbuf: 8192 floats (32 KB) [ksw][b][col][g]
#define OFF_BH   (OFF_PB + 8192)    // 16 floats
#define SMEM_FLOATS (OFF_BH + 16)
#define SMEM_BYTES  (SMEM_FLOATS * 4)

__device__ float g_xg[(size_t)SS * BB * G4];   // x-gate scratch [s][b][hcol*4+gate]
__device__ float g_ht[2][HH * BB];             // transposed h double-buffer [par][k][b]
__device__ unsigned g_flag[GRID_B * 32];       // per-CTA step flags, 128B apart

__global__ void reset_sync() {
    if (threadIdx.x < GRID_B) g_flag[threadIdx.x * 32] = 0u;
}

// ---------------- f32x2 helpers (sm_100+) ----------------
__device__ __forceinline__ unsigned long long pack2(float x, float y) {
    unsigned long long r;
    asm("mov.b64 %0, {%1, %2};" : "=l"(r) : "f"(x), "f"(y));
    return r;
}
__device__ __forceinline__ unsigned long long dup2(float x) { return pack2(x, x); }
__device__ __forceinline__ void unpack2(unsigned long long v, float& x, float& y) {
    asm("mov.b64 {%0, %1}, %2;" : "=f"(x), "=f"(y) : "l"(v));
}
__device__ __forceinline__ unsigned long long fma2(unsigned long long a,
                                                   unsigned long long b,
                                                   unsigned long long c) {
    unsigned long long d;
    asm("fma.rn.f32x2 %0, %1, %2, %3;" : "=l"(d) : "l"(a), "l"(b), "l"(c));
    return d;
}

// ---------------- scoped sync helpers ----------------
__device__ __forceinline__ void red_release_gpu_add(unsigned* p, unsigned v) {
    asm volatile("red.release.gpu.global.add.u32 [%0], %1;" :: "l"(p), "r"(v) : "memory");
}
__device__ __forceinline__ unsigned ld_acquire_gpu(const unsigned* p) {
    unsigned v;
    asm volatile("ld.acquire.gpu.global.u32 %0, [%1];" : "=r"(v) : "l"(p) : "memory");
    return v;
}

__device__ __forceinline__ float fast_sig(float x) {
    float cx = fmaxf(fminf(x, 30.f), -30.f);
    return __fdividef(1.f, 1.f + __expf(-cx));
}
__device__ __forceinline__ float fast_tanh(float x) {
    float ax = fminf(fabsf(x), 12.f);
    float e  = __expf(2.f * ax);
    float r  = __fdividef(e - 1.f, e + 1.f);
    return copysignf(r, x);
}

// ---------------------------------------------------------------------------
// Kernel A: x_gates[s][b][j4] = x[b][s][:] . Wrow(j4) + bi ; j4 = hcol*4+gate
// (unchanged)
// ---------------------------------------------------------------------------
#define AST 66
#define BST 72

__global__ void __launch_bounds__(256) gemm_input(
    const float* __restrict__ x,
    const float* __restrict__ W0, const float* __restrict__ W1,
    const float* __restrict__ W2, const float* __restrict__ W3,
    const float* __restrict__ b0, const float* __restrict__ b1,
    const float* __restrict__ b2, const float* __restrict__ b3)
{
    __shared__ unsigned long long As2[16 * AST];
    __shared__ float              Bs [16 * BST];

    const int t  = threadIdx.x;
    const int m0 = blockIdx.y * 64;
    const int n0 = blockIdx.x * 64;
    const int tx = t & 15, ty = t >> 4;

    const int lr = t >> 2;
    const int lc = (t & 3) * 4;

    const int m    = m0 + lr;
    const int bidx = m & 63, sidx = m >> 6;
    const float* xrow = x + ((size_t)bidx * SS + sidx) * II;

    const int n = n0 + lr;
    const float* Wg[4] = {W0, W1, W2, W3};
    const float* wrow  = Wg[n & 3] + (size_t)(n >> 2) * II;

    unsigned long long a2[4][2];
    #pragma unroll
    for (int i = 0; i < 4; ++i) { a2[i][0] = 0ull; a2[i][1] = 0ull; }

    for (int k0 = 0; k0 < II; k0 += 16) {
        float4 av = *(const float4*)(xrow + k0 + lc);
        float4 bv = *(const float4*)(wrow + k0 + lc);
        __syncthreads();
        As2[(lc+0)*AST + lr] = dup2(av.x); As2[(lc+1)*AST + lr] = dup2(av.y);
        As2[(lc+2)*AST + lr] = dup2(av.z); As2[(lc+3)*AST + lr] = dup2(av.w);
        Bs [(lc+0)*BST + lr] = bv.x;       Bs [(lc+1)*BST + lr] = bv.y;
        Bs [(lc+2)*BST + lr] = bv.z;       Bs [(lc+3)*BST + lr] = bv.w;
        __syncthreads();
        #pragma unroll
        for (int kk = 0; kk < 16; ++kk) {
            ulonglong2 aA = *(const ulonglong2*)&As2[kk*AST + ty*4];
            ulonglong2 aB = *(const ulonglong2*)&As2[kk*AST + ty*4 + 2];
            ulonglong2 w  = *(const ulonglong2*)&Bs [kk*BST + tx*4];
            a2[0][0] = fma2(aA.x, w.x, a2[0][0]); a2[0][1] = fma2(aA.x, w.y, a2[0][1]);
            a2[1][0] = fma2(aA.y, w.x, a2[1][0]); a2[1][1] = fma2(aA.y, w.y, a2[1][1]);
            a2[2][0] = fma2(aB.x, w.x, a2[2][0]); a2[2][1] = fma2(aB.x, w.y, a2[2][1]);
            a2[3][0] = fma2(aB.y, w.x, a2[3][0]); a2[3][1] = fma2(aB.y, w.y, a2[3][1]);
        }
    }

    const int hcol = (n0 + tx*4) >> 2;
    const float bias0 = b0[hcol], bias1 = b1[hcol], bias2 = b2[hcol], bias3 = b3[hcol];
    #pragma unroll
    for (int i = 0; i < 4; ++i) {
        const int mi = m0 + ty*4 + i;
        const size_t o = (size_t)(mi >> 6) * (BB*G4) + (size_t)(mi & 63) * G4 + n0 + tx*4;
        float f0, f1, f2, f3;
        unpack2(a2[i][0], f0, f1);
        unpack2(a2[i][1], f2, f3);
        float4 v;
        v.x = f0 + bias0; v.y = f1 + bias1; v.z = f2 + bias2; v.w = f3 + bias3;
        *(float4*)&g_xg[o] = v;
    }
}

// ---------------------------------------------------------------------------
// Kernel B: persistent recurrent LSTM. FFMA2 inner loop, pipelined staging,
// PER-PRODUCER flag sync (no global barrier): warp ksw waits only on the 16
// CTAs producing its h chunk. WAR safety of the 2-deep g_ht buffer follows
// because a CTA writes h(s) only after all its warps' waits covered all 128
// flags >= s (=> everyone finished staging h(s-2)).
// ---------------------------------------------------------------------------
#define COMPUTE16(kk0)                                                        \
    _Pragma("unroll")                                                         \
    for (int kk = (kk0); kk < (kk0) + 16; ++kk) {                             \
        ulonglong2 hA = *(const ulonglong2*)(hb + (size_t)kk*64);             \
        ulonglong2 hB = *(const ulonglong2*)(hb + (size_t)kk*64 + 4);         \
        ulonglong2 w0 = *(const ulonglong2*)(wb + kk*16);                     \
        ulonglong2 w1 = *(const ulonglong2*)(wb + kk*16 + 2);                 \
        a0[0]=fma2(hA.x,w0.x,a0[0]); a0[1]=fma2(hA.y,w0.x,a0[1]);             \
        a0[2]=fma2(hB.x,w0.x,a0[2]); a0[3]=fma2(hB.y,w0.x,a0[3]);             \
        a1[0]=fma2(hA.x,w0.y,a1[0]); a1[1]=fma2(hA.y,w0.y,a1[1]);             \
        a1[2]=fma2(hB.x,w0.y,a1[2]); a1[3]=fma2(hB.y,w0.y,a1[3]);             \
        a2[0]=fma2(hA.x,w1.x,a2[0]); a2[1]=fma2(hA.y,w1.x,a2[1]);             \
        a2[2]=fma2(hB.x,w1.x,a2[2]); a2[3]=fma2(hB.y,w1.x,a2[3]);             \
        a3[0]=fma2(hA.x,w1.y,a3[0]); a3[1]=fma2(hA.y,w1.y,a3[1]);             \
        a3[2]=fma2(hB.x,w1.y,a3[2]); a3[3]=fma2(hB.y,w1.y,a3[3]);             \
    }

__global__ void __launch_bounds__(TPB, 1) lstm_rec(
    const float* __restrict__ Wh0, const float* __restrict__ Wh1,
    const float* __restrict__ Wh2, const float* __restrict__ Wh3,
    const float* __restrict__ bh0, const float* __restrict__ bh1,
    const float* __restrict__ bh2, const float* __restrict__ bh3,
    float* __restrict__ out)
{
    extern __shared__ float sm[];
    float*              h_sh = sm + OFF_H;                          // [512][64]
    unsigned long long* wds  = (unsigned long long*)(sm + OFF_WD);  // [k][col][g]
    float*              pbuf = sm + OFF_PB;                          // [ksw][b][col][g]
    float*              bhs  = sm + OFF_BH;

    const int ct   = blockIdx.x;
    const int t    = threadIdx.x;
    const int ksw  = t >> 5;          // warp id = K-chunk id
    const int lane = t & 31;
    const int bg   = (t >> 2) & 7;    // batch group (8 batches)
    const int col  = t & 3;           // h-column within CTA (4 gates)
    const int rb   = t >> 2;          // reduce-phase batch
    const int hc   = ct * 4 + col;

    // Stage duplicated Wh slice + bh (once).
    {
        const float* Whg[4] = {Wh0, Wh1, Wh2, Wh3};
        for (int i = t; i < 8192; i += TPB) {
            const int k = i >> 4, c2 = (i >> 2) & 3, g = i & 3;
            wds[i] = dup2(Whg[g][(size_t)(ct*4 + c2) * HH + k]);
        }
        if (t < 16) {
            const float* bg4[4] = {bh0, bh1, bh2, bh3};
            bhs[t] = bg4[t & 3][ct*4 + (t >> 2)];
        }
    }
    __syncthreads();

    const float bx = bhs[col*4 + 0], by = bhs[col*4 + 1];
    const float bz = bhs[col*4 + 2], bw = bhs[col*4 + 3];

    float c = 0.f;
    float* hlast = out + BSH;
    float* clast = hlast + BB*HH;

    const float*              hb = h_sh + ksw*64*64 + bg*8;
    const unsigned long long* wb = wds  + ksw*64*16 + col*4;
    float*       pb = pbuf + ksw*1024 + col*4;        // + b*16 per batch
    const float* pr = pbuf + rb*16 + col*4;           // + kw*1024 per chunk
    const float* xg_base = g_xg + (size_t)rb * G4 + ct*16 + col*4;

    const int base = ksw * 1024;                       // warp's float4 region
    // this warp's 16 producer CTAs: lanes 0..15 each own one flag
    const unsigned* myflag = (lane < 16) ? (g_flag + (ksw*16 + lane)*32) : 0;

    for (int s = 0; s < SS; ++s) {
        // prefetch x-gate for reduce phase
        float4 xgv = *(const float4*)(xg_base + (size_t)s * (BB*G4));

        unsigned long long a0[4], a1[4], a2[4], a3[4];
        #pragma unroll
        for (int j = 0; j < 4; ++j) { a0[j]=0ull; a1[j]=0ull; a2[j]=0ull; a3[j]=0ull; }

        if (s) {
            // Fine-grained wait: only this warp's 16 producers must have
            // published h(s-1)  (flag[p] == number of h vectors written).
            if (lane < 16) {
                while (ld_acquire_gpu(myflag) < (unsigned)s) { }
            }
            __syncwarp();

            // Pipelined staging of warp-private 64-k chunk of h(s-1).
            const float4* s4 = (const float4*)g_ht[(s - 1) & 1];
            float4*       d4 = (float4*)sm;
            float4 r0[8], r1[8];

            #pragma unroll
            for (int j = 0; j < 8; ++j)                           // Q0 loads
                r0[j] = __ldcg(s4 + base + j*32 + lane);
            #pragma unroll
            for (int j = 0; j < 8; ++j)                           // Q1 loads
                r1[j] = __ldcg(s4 + base + 256 + j*32 + lane);
            #pragma unroll
            for (int j = 0; j < 8; ++j)                           // STS Q0
                d4[base + j*32 + lane] = r0[j];
            __syncwarp();

            #pragma unroll
            for (int j = 0; j < 8; ++j)                           // Q2 loads
                r0[j] = __ldcg(s4 + base + 512 + j*32 + lane);
            COMPUTE16(0)                                          // compute Q0

            #pragma unroll
            for (int j = 0; j < 8; ++j)                           // STS Q1
                d4[base + 256 + j*32 + lane] = r1[j];
            __syncwarp();
            #pragma unroll
            for (int j = 0; j < 8; ++j)                           // Q3 loads
                r1[j] = __ldcg(s4 + base + 768 + j*32 + lane);
            COMPUTE16(16)                                         // compute Q1

            #pragma unroll
            for (int j = 0; j < 8; ++j)                           // STS Q2
                d4[base + 512 + j*32 + lane] = r0[j];
            __syncwarp();
            COMPUTE16(32)                                         // compute Q2

            #pragma unroll
            for (int j = 0; j < 8; ++j)                           // STS Q3
                d4[base + 768 + j*32 + lane] = r1[j];
            __syncwarp();
            COMPUTE16(48)                                         // compute Q3
        }

        // Write partials: pbuf[ksw][b][col][0..3] (float4 per batch)
        #pragma unroll
        for (int j = 0; j < 4; ++j) {
            float f0x,f0y,f1x,f1y,f2x,f2y,f3x,f3y;
            unpack2(a0[j], f0x, f0y); unpack2(a1[j], f1x, f1y);
            unpack2(a2[j], f2x, f2y); unpack2(a3[j], f3x, f3y);
            const int b = bg*8 + 2*j;
            float4 v0; v0.x=f0x; v0.y=f1x; v0.z=f2x; v0.w=f3x;
            float4 v1; v1.x=f0y; v1.y=f1y; v1.z=f2y; v1.w=f3y;
            *(float4*)(pb + (size_t)b*16)       = v0;
            *(float4*)(pb + (size_t)(b+1)*16)   = v1;
        }
        __syncthreads();   // S1: partials visible (joins all warps' waits too)

        // Reduce across 8 K-chunks + pointwise
        float4 g4;
        g4.x = xgv.x + bx; g4.y = xgv.y + by; g4.z = xgv.z + bz; g4.w = xgv.w + bw;
        #pragma unroll
        for (int kw = 0; kw < 8; ++kw) {
            float4 v = *(const float4*)(pr + kw*1024);
            g4.x += v.x; g4.y += v.y; g4.z += v.z; g4.w += v.w;
        }

        const float ig = fast_sig(g4.x);
        const float fg = fast_sig(g4.y);
        const float gv = fast_tanh(g4.z);
        const float og = fast_sig(g4.w);
        c = fg * c + ig * gv;
        const float h = og * fast_tanh(c);

        out[(size_t)rb * SH + (size_t)s * HH + hc] = h;
        g_ht[s & 1][hc*64 + rb] = h;
        if (s == SS - 1) hlast[rb*HH + hc] = h;

        __syncthreads();   // S2: h stores ordered before flag release; also
                           // guards pbuf WAR for next step's partial writes
        if (t == 0) red_release_gpu_add(&g_flag[ct*32], 1u);
    }
    clast[rb*HH + hc] = c;
}

// ---------------------------------------------------------------------------
// Launch
// ---------------------------------------------------------------------------
extern "C" void kernel_launch(void* const* d_in, const int* in_sizes, int n_in,
                              void* d_out, int out_size)
{
    const float* x = (const float*)d_in[0];
    const float *Wp[8], *bp[8];
    if (n_in >= 17 && in_sizes[2] == HH) {
        for (int p = 0; p < 8; ++p) { Wp[p] = (const float*)d_in[1 + 2*p];
                                      bp[p] = (const float*)d_in[2 + 2*p]; }
    } else {
        for (int p = 0; p < 8; ++p) { Wp[p] = (const float*)d_in[1 + p];
                                      bp[p] = (const float*)d_in[9 + p]; }
    }
    // pairs: 0=ii,1=hi,2=if,3=hf,4=ig,5=hg,6=io,7=ho ; gate order i,f,g,o
    const float* Wi[4] = {Wp[0], Wp[2], Wp[4], Wp[6]};
    const float* Wh[4] = {Wp[1], Wp[3], Wp[5], Wp[7]};
    const float* bi[4] = {bp[0], bp[2], bp[4], bp[6]};
    const float* bh[4] = {bp[1], bp[3], bp[5], bp[7]};
    float* out = (float*)d_out;

    dim3 gA(G4 / 64, (SS * BB) / 64);
    gemm_input<<<gA, 256>>>(x, Wi[0], Wi[1], Wi[2], Wi[3],
                               bi[0], bi[1], bi[2], bi[3]);

    reset_sync<<<1, 128>>>();

    cudaFuncSetAttribute(lstm_rec, cudaFuncAttributeMaxDynamicSharedMemorySize,
                         SMEM_BYTES);
    lstm_rec<<<GRID_B, TPB, SMEM_BYTES>>>(Wh[0], Wh[1], Wh[2], Wh[3],
                                          bh[0], bh[1], bh[2], bh[3], out);
}

// round 8
// speedup vs baseline: 1.1870x; 1.1870x over previous
#include <cuda_runtime.h>
#include <cstdint>
#include <cstddef>

// Problem constants
#define BB   64
#define SS   1024
#define II   256
#define HH   512
#define G4   2048              // 4*HH
#define SH   (SS*HH)
#define BSH  ((size_t)BB*SH)

// Recurrent kernel config
#define GRID_B 128             // CTAs; each owns 4 h-columns
#define TPB    256

// SMEM layout (float indices)
#define OFF_H    0                  // h_sh [512][64] floats (128 KB)
#define OFF_WD   (512*64)           // wds: 8192 ull (64 KB) = 16384 floats
#define OFF_PB   (OFF_WD + 16384)   // pbuf: 8192 floats (32 KB) [ksw][b][col][g]
#define OFF_BH   (OFF_PB + 8192)    // 16 floats
#define SMEM_FLOATS (OFF_BH + 16)
#define SMEM_BYTES  (SMEM_FLOATS * 4)

__device__ float g_xg[(size_t)SS * BB * G4];   // x-gate scratch [s][b][hcol*4+gate]
__device__ float g_ht[2][HH * BB];             // transposed h double-buffer [par][k][b]
__device__ unsigned g_leaf[8 * 32];            // tree-barrier leaves, 128B apart
__device__ unsigned g_root;                    // tree-barrier root

__global__ void reset_sync() {
    if (threadIdx.x < 8) g_leaf[threadIdx.x * 32] = 0u;
    if (threadIdx.x == 8) g_root = 0u;
}

// ---------------- f32x2 helpers (sm_100+) ----------------
__device__ __forceinline__ unsigned long long pack2(float x, float y) {
    unsigned long long r;
    asm("mov.b64 %0, {%1, %2};" : "=l"(r) : "f"(x), "f"(y));
    return r;
}
__device__ __forceinline__ unsigned long long dup2(float x) { return pack2(x, x); }
__device__ __forceinline__ void unpack2(unsigned long long v, float& x, float& y) {
    asm("mov.b64 {%0, %1}, %2;" : "=f"(x), "=f"(y) : "l"(v));
}
__device__ __forceinline__ unsigned long long fma2(unsigned long long a,
                                                   unsigned long long b,
                                                   unsigned long long c) {
    unsigned long long d;
    asm("fma.rn.f32x2 %0, %1, %2, %3;" : "=l"(d) : "l"(a), "l"(b), "l"(c));
    return d;
}

// ---------------- scoped sync helpers ----------------
__device__ __forceinline__ unsigned atom_acqrel_add(unsigned* p, unsigned v) {
    unsigned old;
    asm volatile("atom.acq_rel.gpu.global.add.u32 %0, [%1], %2;"
                 : "=r"(old) : "l"(p), "r"(v) : "memory");
    return old;
}
__device__ __forceinline__ void red_release_gpu_add(unsigned* p, unsigned v) {
    asm volatile("red.release.gpu.global.add.u32 [%0], %1;" :: "l"(p), "r"(v) : "memory");
}
__device__ __forceinline__ unsigned ld_acquire_gpu(const unsigned* p) {
    unsigned v;
    asm volatile("ld.acquire.gpu.global.u32 %0, [%1];" : "=r"(v) : "l"(p) : "memory");
    return v;
}

__device__ __forceinline__ float fast_sig(float x) {
    float cx = fmaxf(fminf(x, 30.f), -30.f);
    return __fdividef(1.f, 1.f + __expf(-cx));
}
__device__ __forceinline__ float fast_tanh(float x) {
    float ax = fminf(fabsf(x), 12.f);
    float e  = __expf(2.f * ax);
    float r  = __fdividef(e - 1.f, e + 1.f);
    return copysignf(r, x);
}

// ---------------------------------------------------------------------------
// Kernel A: x_gates[s][b][j4] = x[b][s][:] . Wrow(j4) + bi ; j4 = hcol*4+gate
// (unchanged)
// ---------------------------------------------------------------------------
#define AST 66
#define BST 72

__global__ void __launch_bounds__(256) gemm_input(
    const float* __restrict__ x,
    const float* __restrict__ W0, const float* __restrict__ W1,
    const float* __restrict__ W2, const float* __restrict__ W3,
    const float* __restrict__ b0, const float* __restrict__ b1,
    const float* __restrict__ b2, const float* __restrict__ b3)
{
    __shared__ unsigned long long As2[16 * AST];
    __shared__ float              Bs [16 * BST];

    const int t  = threadIdx.x;
    const int m0 = blockIdx.y * 64;
    const int n0 = blockIdx.x * 64;
    const int tx = t & 15, ty = t >> 4;

    const int lr = t >> 2;
    const int lc = (t & 3) * 4;

    const int m    = m0 + lr;
    const int bidx = m & 63, sidx = m >> 6;
    const float* xrow = x + ((size_t)bidx * SS + sidx) * II;

    const int n = n0 + lr;
    const float* Wg[4] = {W0, W1, W2, W3};
    const float* wrow  = Wg[n & 3] + (size_t)(n >> 2) * II;

    unsigned long long a2[4][2];
    #pragma unroll
    for (int i = 0; i < 4; ++i) { a2[i][0] = 0ull; a2[i][1] = 0ull; }

    for (int k0 = 0; k0 < II; k0 += 16) {
        float4 av = *(const float4*)(xrow + k0 + lc);
        float4 bv = *(const float4*)(wrow + k0 + lc);
        __syncthreads();
        As2[(lc+0)*AST + lr] = dup2(av.x); As2[(lc+1)*AST + lr] = dup2(av.y);
        As2[(lc+2)*AST + lr] = dup2(av.z); As2[(lc+3)*AST + lr] = dup2(av.w);
        Bs [(lc+0)*BST + lr] = bv.x;       Bs [(lc+1)*BST + lr] = bv.y;
        Bs [(lc+2)*BST + lr] = bv.z;       Bs [(lc+3)*BST + lr] = bv.w;
        __syncthreads();
        #pragma unroll
        for (int kk = 0; kk < 16; ++kk) {
            ulonglong2 aA = *(const ulonglong2*)&As2[kk*AST + ty*4];
            ulonglong2 aB = *(const ulonglong2*)&As2[kk*AST + ty*4 + 2];
            ulonglong2 w  = *(const ulonglong2*)&Bs [kk*BST + tx*4];
            a2[0][0] = fma2(aA.x, w.x, a2[0][0]); a2[0][1] = fma2(aA.x, w.y, a2[0][1]);
            a2[1][0] = fma2(aA.y, w.x, a2[1][0]); a2[1][1] = fma2(aA.y, w.y, a2[1][1]);
            a2[2][0] = fma2(aB.x, w.x, a2[2][0]); a2[2][1] = fma2(aB.x, w.y, a2[2][1]);
            a2[3][0] = fma2(aB.y, w.x, a2[3][0]); a2[3][1] = fma2(aB.y, w.y, a2[3][1]);
        }
    }

    const int hcol = (n0 + tx*4) >> 2;
    const float bias0 = b0[hcol], bias1 = b1[hcol], bias2 = b2[hcol], bias3 = b3[hcol];
    #pragma unroll
    for (int i = 0; i < 4; ++i) {
        const int mi = m0 + ty*4 + i;
        const size_t o = (size_t)(mi >> 6) * (BB*G4) + (size_t)(mi & 63) * G4 + n0 + tx*4;
        float f0, f1, f2, f3;
        unpack2(a2[i][0], f0, f1);
        unpack2(a2[i][1], f2, f3);
        float4 v;
        v.x = f0 + bias0; v.y = f1 + bias1; v.z = f2 + bias2; v.w = f3 + bias3;
        *(float4*)&g_xg[o] = v;
    }
}

// ---------------------------------------------------------------------------
// Kernel B: persistent recurrent LSTM (R5 structure) with TREE barrier:
// arrivals go to 8 leaf counters (16 CTAs each, parallel); the 16th arriver
// of a leaf promotes (release) to the root; 1 thread/CTA acquire-polls root.
// ---------------------------------------------------------------------------
#define COMPUTE16(kk0)                                                        \
    _Pragma("unroll")                                                         \
    for (int kk = (kk0); kk < (kk0) + 16; ++kk) {                             \
        ulonglong2 hA = *(const ulonglong2*)(hb + (size_t)kk*64);             \
        ulonglong2 hB = *(const ulonglong2*)(hb + (size_t)kk*64 + 4);         \
        ulonglong2 w0 = *(const ulonglong2*)(wb + kk*16);                     \
        ulonglong2 w1 = *(const ulonglong2*)(wb + kk*16 + 2);                 \
        a0[0]=fma2(hA.x,w0.x,a0[0]); a0[1]=fma2(hA.y,w0.x,a0[1]);             \
        a0[2]=fma2(hB.x,w0.x,a0[2]); a0[3]=fma2(hB.y,w0.x,a0[3]);             \
        a1[0]=fma2(hA.x,w0.y,a1[0]); a1[1]=fma2(hA.y,w0.y,a1[1]);             \
        a1[2]=fma2(hB.x,w0.y,a1[2]); a1[3]=fma2(hB.y,w0.y,a1[3]);             \
        a2[0]=fma2(hA.x,w1.x,a2[0]); a2[1]=fma2(hA.y,w1.x,a2[1]);             \
        a2[2]=fma2(hB.x,w1.x,a2[2]); a2[3]=fma2(hB.y,w1.x,a2[3]);             \
        a3[0]=fma2(hA.x,w1.y,a3[0]); a3[1]=fma2(hA.y,w1.y,a3[1]);             \
        a3[2]=fma2(hB.x,w1.y,a3[2]); a3[3]=fma2(hB.y,w1.y,a3[3]);             \
    }

__global__ void __launch_bounds__(TPB, 1) lstm_rec(
    const float* __restrict__ Wh0, const float* __restrict__ Wh1,
    const float* __restrict__ Wh2, const float* __restrict__ Wh3,
    const float* __restrict__ bh0, const float* __restrict__ bh1,
    const float* __restrict__ bh2, const float* __restrict__ bh3,
    float* __restrict__ out)
{
    extern __shared__ float sm[];
    float*              h_sh = sm + OFF_H;                          // [512][64]
    unsigned long long* wds  = (unsigned long long*)(sm + OFF_WD);  // [k][col][g]
    float*              pbuf = sm + OFF_PB;                          // [ksw][b][col][g]
    float*              bhs  = sm + OFF_BH;

    const int ct   = blockIdx.x;
    const int t    = threadIdx.x;
    const int ksw  = t >> 5;          // warp id = K-chunk id
    const int lane = t & 31;
    const int bg   = (t >> 2) & 7;    // batch group (8 batches)
    const int col  = t & 3;           // h-column within CTA (4 gates)
    const int rb   = t >> 2;          // reduce-phase batch
    const int hc   = ct * 4 + col;

    // Stage duplicated Wh slice + bh (once).
    {
        const float* Whg[4] = {Wh0, Wh1, Wh2, Wh3};
        for (int i = t; i < 8192; i += TPB) {
            const int k = i >> 4, c2 = (i >> 2) & 3, g = i & 3;
            wds[i] = dup2(Whg[g][(size_t)(ct*4 + c2) * HH + k]);
        }
        if (t < 16) {
            const float* bg4[4] = {bh0, bh1, bh2, bh3};
            bhs[t] = bg4[t & 3][ct*4 + (t >> 2)];
        }
    }
    __syncthreads();

    const float bx = bhs[col*4 + 0], by = bhs[col*4 + 1];
    const float bz = bhs[col*4 + 2], bw = bhs[col*4 + 3];

    float c = 0.f;
    float* hlast = out + BSH;
    float* clast = hlast + BB*HH;

    const float*              hb = h_sh + ksw*64*64 + bg*8;
    const unsigned long long* wb = wds  + ksw*64*16 + col*4;
    float*       pb = pbuf + ksw*1024 + col*4;        // + b*16 per batch
    const float* pr = pbuf + rb*16 + col*4;           // + kw*1024 per chunk
    const float* xg_base = g_xg + (size_t)rb * G4 + ct*16 + col*4;

    const int base = ksw * 1024;                       // warp's float4 region
    unsigned* leaf = &g_leaf[(ct >> 4) * 32];

    for (int s = 0; s < SS; ++s) {
        // prefetch x-gate for reduce phase
        float4 xgv = *(const float4*)(xg_base + (size_t)s * (BB*G4));

        unsigned long long a0[4], a1[4], a2[4], a3[4];
        #pragma unroll
        for (int j = 0; j < 4; ++j) { a0[j]=0ull; a1[j]=0ull; a2[j]=0ull; a3[j]=0ull; }

        if (s) {
            // Pipelined staging of warp-private 64-k chunk of h(s-1).
            const float4* s4 = (const float4*)g_ht[(s - 1) & 1];
            float4*       d4 = (float4*)sm;
            float4 r0[8], r1[8];

            #pragma unroll
            for (int j = 0; j < 8; ++j)                           // Q0 loads
                r0[j] = __ldcg(s4 + base + j*32 + lane);
            #pragma unroll
            for (int j = 0; j < 8; ++j)                           // Q1 loads
                r1[j] = __ldcg(s4 + base + 256 + j*32 + lane);
            #pragma unroll
            for (int j = 0; j < 8; ++j)                           // STS Q0
                d4[base + j*32 + lane] = r0[j];
            __syncwarp();

            #pragma unroll
            for (int j = 0; j < 8; ++j)                           // Q2 loads
                r0[j] = __ldcg(s4 + base + 512 + j*32 + lane);
            COMPUTE16(0)                                          // compute Q0

            #pragma unroll
            for (int j = 0; j < 8; ++j)                           // STS Q1
                d4[base + 256 + j*32 + lane] = r1[j];
            __syncwarp();
            #pragma unroll
            for (int j = 0; j < 8; ++j)                           // Q3 loads
                r1[j] = __ldcg(s4 + base + 768 + j*32 + lane);
            COMPUTE16(16)                                         // compute Q1

            #pragma unroll
            for (int j = 0; j < 8; ++j)                           // STS Q2
                d4[base + 512 + j*32 + lane] = r0[j];
            __syncwarp();
            COMPUTE16(32)                                         // compute Q2

            #pragma unroll
            for (int j = 0; j < 8; ++j)                           // STS Q3
                d4[base + 768 + j*32 + lane] = r1[j];
            __syncwarp();
            COMPUTE16(48)                                         // compute Q3
        }

        // Write partials: pbuf[ksw][b][col][0..3] (float4 per batch)
        #pragma unroll
        for (int j = 0; j < 4; ++j) {
            float f0x,f0y,f1x,f1y,f2x,f2y,f3x,f3y;
            unpack2(a0[j], f0x, f0y); unpack2(a1[j], f1x, f1y);
            unpack2(a2[j], f2x, f2y); unpack2(a3[j], f3x, f3y);
            const int b = bg*8 + 2*j;
            float4 v0; v0.x=f0x; v0.y=f1x; v0.z=f2x; v0.w=f3x;
            float4 v1; v1.x=f0y; v1.y=f1y; v1.z=f2y; v1.w=f3y;
            *(float4*)(pb + (size_t)b*16)       = v0;
            *(float4*)(pb + (size_t)(b+1)*16)   = v1;
        }
        __syncthreads();   // S1: partials visible

        // Reduce across 8 K-chunks + pointwise
        float4 g4;
        g4.x = xgv.x + bx; g4.y = xgv.y + by; g4.z = xgv.z + bz; g4.w = xgv.w + bw;
        #pragma unroll
        for (int kw = 0; kw < 8; ++kw) {
            float4 v = *(const float4*)(pr + kw*1024);
            g4.x += v.x; g4.y += v.y; g4.z += v.z; g4.w += v.w;
        }

        const float ig = fast_sig(g4.x);
        const float fg = fast_sig(g4.y);
        const float gv = fast_tanh(g4.z);
        const float og = fast_sig(g4.w);
        c = fg * c + ig * gv;
        const float h = og * fast_tanh(c);

        out[(size_t)rb * SH + (size_t)s * HH + hc] = h;
        g_ht[s & 1][hc*64 + rb] = h;
        if (s == SS - 1) hlast[rb*HH + hc] = h;

        __syncthreads();   // S2: h stores ordered before arrival
        if (t == 0) {
            // Tree arrival: leaf (acq_rel), 16th arriver promotes to root.
            unsigned old = atom_acqrel_add(leaf, 1u);
            if ((old & 15u) == 15u) red_release_gpu_add(&g_root, 1u);
            if (s + 1 < SS) {
                const unsigned tgt = (unsigned)(s + 1) * 8u;
                while (ld_acquire_gpu(&g_root) < tgt) { __nanosleep(20); }
            }
        }
        __syncthreads();   // S3: hand off acquire to whole CTA
    }
    clast[rb*HH + hc] = c;
}

// ---------------------------------------------------------------------------
// Launch
// ---------------------------------------------------------------------------
extern "C" void kernel_launch(void* const* d_in, const int* in_sizes, int n_in,
                              void* d_out, int out_size)
{
    const float* x = (const float*)d_in[0];
    const float *Wp[8], *bp[8];
    if (n_in >= 17 && in_sizes[2] == HH) {
        for (int p = 0; p < 8; ++p) { Wp[p] = (const float*)d_in[1 + 2*p];
                                      bp[p] = (const float*)d_in[2 + 2*p]; }
    } else {
        for (int p = 0; p < 8; ++p) { Wp[p] = (const float*)d_in[1 + p];
                                      bp[p] = (const float*)d_in[9 + p]; }
    }
    // pairs: 0=ii,1=hi,2=if,3=hf,4=ig,5=hg,6=io,7=ho ; gate order i,f,g,o
    const float* Wi[4] = {Wp[0], Wp[2], Wp[4], Wp[6]};
    const float* Wh[4] = {Wp[1], Wp[3], Wp[5], Wp[7]};
    const float* bi[4] = {bp[0], bp[2], bp[4], bp[6]};
    const float* bh[4] = {bp[1], bp[3], bp[5], bp[7]};
    float* out = (float*)d_out;

    dim3 gA(G4 / 64, (SS * BB) / 64);
    gemm_input<<<gA, 256>>>(x, Wi[0], Wi[1], Wi[2], Wi[3],
                               bi[0], bi[1], bi[2], bi[3]);

    reset_sync<<<1, 32>>>();

    cudaFuncSetAttribute(lstm_rec, cudaFuncAttributeMaxDynamicSharedMemorySize,
                         SMEM_BYTES);
    lstm_rec<<<GRID_B, TPB, SMEM_BYTES>>>(Wh[0], Wh[1], Wh[2], Wh[3],
                                          bh[0], bh[1], bh[2], bh[3], out);
}

// round 9
// speedup vs baseline: 1.4486x; 1.2204x over previous
#include <cuda_runtime.h>
#include <cstdint>
#include <cstddef>

// Problem constants
#define BB   64
#define SS   1024
#define II   256
#define HH   512
#define G4   2048              // 4*HH
#define SH   (SS*HH)
#define BSH  ((size_t)BB*SH)

// Recurrent kernel config
#define GRID_B 128             // CTAs; each owns 4 h-columns
#define TPB    256

// SMEM layout (float indices)
#define OFF_H    0                  // h_sh [512][64] floats (128 KB)
#define OFF_WD   (512*64)           // wds: 8192 ull (64 KB) = 16384 floats
#define OFF_PB   (OFF_WD + 16384)   // pbuf: 8192 floats (32 KB) [ksw][b][col][g]
#define OFF_BH   (OFF_PB + 8192)    // 16 floats
#define SMEM_FLOATS (OFF_BH + 16)
#define SMEM_BYTES  (SMEM_FLOATS * 4)

__device__ float g_xg[(size_t)SS * BB * G4];   // x-gate scratch [s][b][hcol*4+gate]
__device__ float g_ht[2][HH * BB];             // transposed h double-buffer [par][k][b]
__device__ unsigned g_sync;

__global__ void reset_sync() { g_sync = 0u; }

// ---------------- f32x2 helpers (sm_100+) ----------------
__device__ __forceinline__ unsigned long long pack2(float x, float y) {
    unsigned long long r;
    asm("mov.b64 %0, {%1, %2};" : "=l"(r) : "f"(x), "f"(y));
    return r;
}
__device__ __forceinline__ unsigned long long dup2(float x) { return pack2(x, x); }
__device__ __forceinline__ void unpack2(unsigned long long v, float& x, float& y) {
    asm("mov.b64 {%0, %1}, %2;" : "=f"(x), "=f"(y) : "l"(v));
}
__device__ __forceinline__ unsigned long long fma2(unsigned long long a,
                                                   unsigned long long b,
                                                   unsigned long long c) {
    unsigned long long d;
    asm("fma.rn.f32x2 %0, %1, %2, %3;" : "=l"(d) : "l"(a), "l"(b), "l"(c));
    return d;
}
__device__ __forceinline__ unsigned long long add2(unsigned long long a,
                                                   unsigned long long b) {
    unsigned long long d;
    asm("add.rn.f32x2 %0, %1, %2;" : "=l"(d) : "l"(a), "l"(b));
    return d;
}

// ---------------- cp.async helpers ----------------
__device__ __forceinline__ void cp_async16(unsigned smem_addr, const void* gptr) {
    asm volatile("cp.async.cg.shared.global [%0], [%1], 16;"
                 :: "r"(smem_addr), "l"(gptr) : "memory");
}
#define CP_COMMIT()  asm volatile("cp.async.commit_group;" ::: "memory")
#define CP_WAIT(N)   asm volatile("cp.async.wait_group %0;" :: "n"(N) : "memory")

// ---------------- scoped sync helpers ----------------
__device__ __forceinline__ void red_release_gpu_add(unsigned* p, unsigned v) {
    asm volatile("red.release.gpu.global.add.u32 [%0], %1;" :: "l"(p), "r"(v) : "memory");
}
__device__ __forceinline__ unsigned ld_acquire_gpu(const unsigned* p) {
    unsigned v;
    asm volatile("ld.acquire.gpu.global.u32 %0, [%1];" : "=r"(v) : "l"(p) : "memory");
    return v;
}

__device__ __forceinline__ float fast_sig(float x) {
    float cx = fmaxf(fminf(x, 30.f), -30.f);
    return __fdividef(1.f, 1.f + __expf(-cx));
}
__device__ __forceinline__ float fast_tanh(float x) {
    float ax = fminf(fabsf(x), 12.f);
    float e  = __expf(2.f * ax);
    float r  = __fdividef(e - 1.f, e + 1.f);
    return copysignf(r, x);
}

// ---------------------------------------------------------------------------
// Kernel A: x_gates[s][b][j4] = x[b][s][:] . Wrow(j4) + bi ; j4 = hcol*4+gate
// (unchanged)
// ---------------------------------------------------------------------------
#define AST 66
#define BST 72

__global__ void __launch_bounds__(256) gemm_input(
    const float* __restrict__ x,
    const float* __restrict__ W0, const float* __restrict__ W1,
    const float* __restrict__ W2, const float* __restrict__ W3,
    const float* __restrict__ b0, const float* __restrict__ b1,
    const float* __restrict__ b2, const float* __restrict__ b3)
{
    __shared__ unsigned long long As2[16 * AST];
    __shared__ float              Bs [16 * BST];

    const int t  = threadIdx.x;
    const int m0 = blockIdx.y * 64;
    const int n0 = blockIdx.x * 64;
    const int tx = t & 15, ty = t >> 4;

    const int lr = t >> 2;
    const int lc = (t & 3) * 4;

    const int m    = m0 + lr;
    const int bidx = m & 63, sidx = m >> 6;
    const float* xrow = x + ((size_t)bidx * SS + sidx) * II;

    const int n = n0 + lr;
    const float* Wg[4] = {W0, W1, W2, W3};
    const float* wrow  = Wg[n & 3] + (size_t)(n >> 2) * II;

    unsigned long long a2[4][2];
    #pragma unroll
    for (int i = 0; i < 4; ++i) { a2[i][0] = 0ull; a2[i][1] = 0ull; }

    for (int k0 = 0; k0 < II; k0 += 16) {
        float4 av = *(const float4*)(xrow + k0 + lc);
        float4 bv = *(const float4*)(wrow + k0 + lc);
        __syncthreads();
        As2[(lc+0)*AST + lr] = dup2(av.x); As2[(lc+1)*AST + lr] = dup2(av.y);
        As2[(lc+2)*AST + lr] = dup2(av.z); As2[(lc+3)*AST + lr] = dup2(av.w);
        Bs [(lc+0)*BST + lr] = bv.x;       Bs [(lc+1)*BST + lr] = bv.y;
        Bs [(lc+2)*BST + lr] = bv.z;       Bs [(lc+3)*BST + lr] = bv.w;
        __syncthreads();
        #pragma unroll
        for (int kk = 0; kk < 16; ++kk) {
            ulonglong2 aA = *(const ulonglong2*)&As2[kk*AST + ty*4];
            ulonglong2 aB = *(const ulonglong2*)&As2[kk*AST + ty*4 + 2];
            ulonglong2 w  = *(const ulonglong2*)&Bs [kk*BST + tx*4];
            a2[0][0] = fma2(aA.x, w.x, a2[0][0]); a2[0][1] = fma2(aA.x, w.y, a2[0][1]);
            a2[1][0] = fma2(aA.y, w.x, a2[1][0]); a2[1][1] = fma2(aA.y, w.y, a2[1][1]);
            a2[2][0] = fma2(aB.x, w.x, a2[2][0]); a2[2][1] = fma2(aB.x, w.y, a2[2][1]);
            a2[3][0] = fma2(aB.y, w.x, a2[3][0]); a2[3][1] = fma2(aB.y, w.y, a2[3][1]);
        }
    }

    const int hcol = (n0 + tx*4) >> 2;
    const float bias0 = b0[hcol], bias1 = b1[hcol], bias2 = b2[hcol], bias3 = b3[hcol];
    #pragma unroll
    for (int i = 0; i < 4; ++i) {
        const int mi = m0 + ty*4 + i;
        const size_t o = (size_t)(mi >> 6) * (BB*G4) + (size_t)(mi & 63) * G4 + n0 + tx*4;
        float f0, f1, f2, f3;
        unpack2(a2[i][0], f0, f1);
        unpack2(a2[i][1], f2, f3);
        float4 v;
        v.x = f0 + bias0; v.y = f1 + bias1; v.z = f2 + bias2; v.w = f3 + bias3;
        *(float4*)&g_xg[o] = v;
    }
}

// ---------------------------------------------------------------------------
// Kernel B: persistent recurrent LSTM. FFMA2 inner loop; cp.async staged
// h chunks (register-free, 4 commit groups overlapped with compute);
// R5 flat-counter global barrier (measured best).
// ---------------------------------------------------------------------------
#define COMPUTE16(kk0)                                                        \
    _Pragma("unroll")                                                         \
    for (int kk = (kk0); kk < (kk0) + 16; ++kk) {                             \
        ulonglong2 hA = *(const ulonglong2*)(hb + (size_t)kk*64);             \
        ulonglong2 hB = *(const ulonglong2*)(hb + (size_t)kk*64 + 4);         \
        ulonglong2 w0 = *(const ulonglong2*)(wb + kk*16);                     \
        ulonglong2 w1 = *(const ulonglong2*)(wb + kk*16 + 2);                 \
        a0[0]=fma2(hA.x,w0.x,a0[0]); a0[1]=fma2(hA.y,w0.x,a0[1]);             \
        a0[2]=fma2(hB.x,w0.x,a0[2]); a0[3]=fma2(hB.y,w0.x,a0[3]);             \
        a1[0]=fma2(hA.x,w0.y,a1[0]); a1[1]=fma2(hA.y,w0.y,a1[1]);             \
        a1[2]=fma2(hB.x,w0.y,a1[2]); a1[3]=fma2(hB.y,w0.y,a1[3]);             \
        a2[0]=fma2(hA.x,w1.x,a2[0]); a2[1]=fma2(hA.y,w1.x,a2[1]);             \
        a2[2]=fma2(hB.x,w1.x,a2[2]); a2[3]=fma2(hB.y,w1.x,a2[3]);             \
        a3[0]=fma2(hA.x,w1.y,a3[0]); a3[1]=fma2(hA.y,w1.y,a3[1]);             \
        a3[2]=fma2(hB.x,w1.y,a3[2]); a3[3]=fma2(hB.y,w1.y,a3[3]);             \
    }

__global__ void __launch_bounds__(TPB, 1) lstm_rec(
    const float* __restrict__ Wh0, const float* __restrict__ Wh1,
    const float* __restrict__ Wh2, const float* __restrict__ Wh3,
    const float* __restrict__ bh0, const float* __restrict__ bh1,
    const float* __restrict__ bh2, const float* __restrict__ bh3,
    float* __restrict__ out)
{
    extern __shared__ float sm[];
    float*              h_sh = sm + OFF_H;                          // [512][64]
    unsigned long long* wds  = (unsigned long long*)(sm + OFF_WD);  // [k][col][g]
    float*              pbuf = sm + OFF_PB;                          // [ksw][b][col][g]
    float*              bhs  = sm + OFF_BH;

    const int ct   = blockIdx.x;
    const int t    = threadIdx.x;
    const int ksw  = t >> 5;          // warp id = K-chunk id
    const int lane = t & 31;
    const int bg   = (t >> 2) & 7;    // batch group (8 batches)
    const int col  = t & 3;           // h-column within CTA (4 gates)
    const int rb   = t >> 2;          // reduce-phase batch
    const int hc   = ct * 4 + col;

    // Stage duplicated Wh slice + bh (once).
    {
        const float* Whg[4] = {Wh0, Wh1, Wh2, Wh3};
        for (int i = t; i < 8192; i += TPB) {
            const int k = i >> 4, c2 = (i >> 2) & 3, g = i & 3;
            wds[i] = dup2(Whg[g][(size_t)(ct*4 + c2) * HH + k]);
        }
        if (t < 16) {
            const float* bg4[4] = {bh0, bh1, bh2, bh3};
            bhs[t] = bg4[t & 3][ct*4 + (t >> 2)];
        }
    }
    __syncthreads();

    const float bx = bhs[col*4 + 0], by = bhs[col*4 + 1];
    const float bz = bhs[col*4 + 2], bw = bhs[col*4 + 3];

    float c = 0.f;
    float* hlast = out + BSH;
    float* clast = hlast + BB*HH;

    const float*              hb = h_sh + ksw*64*64 + bg*8;
    const unsigned long long* wb = wds  + ksw*64*16 + col*4;
    float*       pb = pbuf + ksw*1024 + col*4;        // + b*16 per batch
    const float* pr = pbuf + rb*16 + col*4;           // + kw*1024 per chunk
    const float* xg_base = g_xg + (size_t)rb * G4 + ct*16 + col*4;

    const int base = ksw * 1024;                       // warp's float4 region
    const unsigned smem_u32 = (unsigned)__cvta_generic_to_shared(sm);

    for (int s = 0; s < SS; ++s) {
        // prefetch x-gate for reduce phase
        float4 xgv = *(const float4*)(xg_base + (size_t)s * (BB*G4));

        unsigned long long a0[4], a1[4], a2[4], a3[4];
        #pragma unroll
        for (int j = 0; j < 4; ++j) { a0[j]=0ull; a1[j]=0ull; a2[j]=0ull; a3[j]=0ull; }

        if (s) {
            // Register-free cp.async staging of this warp's 64-k chunk of
            // h(s-1) (16 KB) in 4 commit groups, overlapped with compute.
            const float4* s4 = (const float4*)g_ht[(s - 1) & 1];
            #pragma unroll
            for (int q = 0; q < 4; ++q) {
                #pragma unroll
                for (int j = 0; j < 8; ++j) {
                    const int idx = base + q*256 + j*32 + lane;   // float4 units
                    cp_async16(smem_u32 + (unsigned)idx * 16u, s4 + idx);
                }
                CP_COMMIT();
            }
            CP_WAIT(3); __syncwarp();
            COMPUTE16(0)
            CP_WAIT(2); __syncwarp();
            COMPUTE16(16)
            CP_WAIT(1); __syncwarp();
            COMPUTE16(32)
            CP_WAIT(0); __syncwarp();
            COMPUTE16(48)
        }

        // Write partials: pbuf[ksw][b][col][0..3] (float4 per batch)
        #pragma unroll
        for (int j = 0; j < 4; ++j) {
            float f0x,f0y,f1x,f1y,f2x,f2y,f3x,f3y;
            unpack2(a0[j], f0x, f0y); unpack2(a1[j], f1x, f1y);
            unpack2(a2[j], f2x, f2y); unpack2(a3[j], f3x, f3y);
            const int b = bg*8 + 2*j;
            float4 v0; v0.x=f0x; v0.y=f1x; v0.z=f2x; v0.w=f3x;
            float4 v1; v1.x=f0y; v1.y=f1y; v1.z=f2y; v1.w=f3y;
            *(float4*)(pb + (size_t)b*16)       = v0;
            *(float4*)(pb + (size_t)(b+1)*16)   = v1;
        }
        __syncthreads();   // S1: partials visible

        // Reduce across 8 K-chunks (f32x2 adds) + pointwise
        unsigned long long gA = pack2(xgv.x + bx, xgv.y + by);
        unsigned long long gB = pack2(xgv.z + bz, xgv.w + bw);
        #pragma unroll
        for (int kw = 0; kw < 8; ++kw) {
            ulonglong2 v = *(const ulonglong2*)(pr + kw*1024);
            gA = add2(gA, v.x);
            gB = add2(gB, v.y);
        }
        float gx, gy, gz, gw;
        unpack2(gA, gx, gy);
        unpack2(gB, gz, gw);

        const float ig = fast_sig(gx);
        const float fg = fast_sig(gy);
        const float gv = fast_tanh(gz);
        const float og = fast_sig(gw);
        c = fg * c + ig * gv;
        const float h = og * fast_tanh(c);

        out[(size_t)rb * SH + (size_t)s * HH + hc] = h;
        g_ht[s & 1][hc*64 + rb] = h;
        if (s == SS - 1) hlast[rb*HH + hc] = h;

        __syncthreads();   // S2: stores ordered before arrival signal
        if (t == 0) {
            red_release_gpu_add(&g_sync, 1u);
            if (s + 1 < SS) {
                const unsigned tgt = (unsigned)(s + 1) * GRID_B;
                while (ld_acquire_gpu(&g_sync) < tgt) { __nanosleep(32); }
            }
        }
        __syncthreads();   // S3: hand off acquire to whole CTA
    }
    clast[rb*HH + hc] = c;
}

// ---------------------------------------------------------------------------
// Launch
// ---------------------------------------------------------------------------
extern "C" void kernel_launch(void* const* d_in, const int* in_sizes, int n_in,
                              void* d_out, int out_size)
{
    const float* x = (const float*)d_in[0];
    const float *Wp[8], *bp[8];
    if (n_in >= 17 && in_sizes[2] == HH) {
        for (int p = 0; p < 8; ++p) { Wp[p] = (const float*)d_in[1 + 2*p];
                                      bp[p] = (const float*)d_in[2 + 2*p]; }
    } else {
        for (int p = 0; p < 8; ++p) { Wp[p] = (const float*)d_in[1 + p];
                                      bp[p] = (const float*)d_in[9 + p]; }
    }
    // pairs: 0=ii,1=hi,2=if,3=hf,4=ig,5=hg,6=io,7=ho ; gate order i,f,g,o
    const float* Wi[4] = {Wp[0], Wp[2], Wp[4], Wp[6]};
    const float* Wh[4] = {Wp[1], Wp[3], Wp[5], Wp[7]};
    const float* bi[4] = {bp[0], bp[2], bp[4], bp[6]};
    const float* bh[4] = {bp[1], bp[3], bp[5], bp[7]};
    float* out = (float*)d_out;

    dim3 gA(G4 / 64, (SS * BB) / 64);
    gemm_input<<<gA, 256>>>(x, Wi[0], Wi[1], Wi[2], Wi[3],
                               bi[0], bi[1], bi[2], bi[3]);

    reset_sync<<<1, 1>>>();

    cudaFuncSetAttribute(lstm_rec, cudaFuncAttributeMaxDynamicSharedMemorySize,
                         SMEM_BYTES);
    lstm_rec<<<GRID_B, TPB, SMEM_BYTES>>>(Wh[0], Wh[1], Wh[2], Wh[3],
                                          bh[0], bh[1], bh[2], bh[3], out);
}